// round 11
// baseline (speedup 1.0000x reference)
#include <cuda_runtime.h>
#include <cuda_bf16.h>
#include <cstdint>

#define BSZ 8192
#define DD  512
#define CC  512
#define MT  32                  // rows per CTA
#define NBLK (BSZ / MT)         // 256 CTAs -> 2 per SM
#define NSTG 16                 // K chunks of 32
#define TH  3.0f
#define SLOTS 16
#define NTH 512

// ---- device scratch ----
__device__ __nv_bfloat16 g_ch[CC * DD];
__device__ float g_cnorm[CC];
__device__ int   g_present[CC];      // zero-init; only 1s written (idempotent)
__device__ float g_rpart[2 * NBLK];
__device__ int   g_rcount;           // reset by last block each call

// ---- main smem layout (bytes) ----
#define SM_CN    0                   // 512 f
#define SM_TG    2048                // 32 i
#define SM_XN    2176                // 32 f
#define SM_RM    2304                // 32 f
#define SM_SCNT  2432                // 32 i
#define SM_CAND  2560                // 32*16 u16 = 1024
#define SM_RED   3584                // 32*8 f = 1024
#define SM_LP    4608                // 32*2 f = 256
#define SM_FIN   4864                // 16 f
#define SM_TILE  5120                // 1024-aligned
#define OFF_A    0                   // 32 rows x 64B = 2048
#define OFF_B    2048                // 512 rows x 64B = 32768
#define STG_B    34816
#define SMEM_BYTES (SM_TILE + 2 * STG_B)   // 74752 -> 2 CTAs/SM

static __device__ __forceinline__ uint32_t s2u(const void* p) {
    uint32_t a;
    asm("{ .reg .u64 t; cvta.to.shared.u64 t, %1; cvt.u32.u64 %0, t; }" : "=r"(a) : "l"(p));
    return a;
}
static __device__ __forceinline__ void cp16(uint32_t dst, const void* src) {
    asm volatile("cp.async.cg.shared.global [%0], [%1], 16;" :: "r"(dst), "l"(src));
}
#define LDSM4(r0, r1, r2, r3, addr)                                             \
    asm volatile("ldmatrix.sync.aligned.m8n8.x4.shared.b16 {%0,%1,%2,%3}, [%4];" \
                 : "=r"(r0), "=r"(r1), "=r"(r2), "=r"(r3) : "r"(addr))
#define MMA(d, a, b0, b1)                                                        \
    asm volatile("mma.sync.aligned.m16n8k16.row.col.f32.bf16.bf16.f32 "          \
                 "{%0,%1,%2,%3},{%4,%5,%6,%7},{%8,%9},{%0,%1,%2,%3};"            \
                 : "+f"((d)[0]), "+f"((d)[1]), "+f"((d)[2]), "+f"((d)[3])        \
                 : "r"((a)[0]), "r"((a)[1]), "r"((a)[2]), "r"((a)[3]),           \
                   "r"(b0), "r"(b1))

static __device__ __forceinline__ uint32_t packbf(float x, float y) {
    return ((uint32_t)__bfloat16_as_ushort(__float2bfloat16(y)) << 16)
         | __bfloat16_as_ushort(__float2bfloat16(x));
}
static __device__ __forceinline__ float sq4(float4 v, float s) {
    s = fmaf(v.x, v.x, s); s = fmaf(v.y, v.y, s);
    s = fmaf(v.z, v.z, s); s = fmaf(v.w, v.w, s);
    return s;
}
static __device__ __forceinline__ float dot512(const float4* xv, const float* crow, int lane) {
    const float4* c4 = (const float4*)crow;
    float s = 0.f;
#pragma unroll
    for (int i = 0; i < 4; i++) {
        float4 c = c4[lane + 32 * i];
        s = fmaf(xv[i].x, c.x, s); s = fmaf(xv[i].y, c.y, s);
        s = fmaf(xv[i].z, c.z, s); s = fmaf(xv[i].w, c.w, s);
    }
#pragma unroll
    for (int o = 16; o > 0; o >>= 1) s += __shfl_xor_sync(0xffffffffu, s, o);
    return s;
}
// 4 concurrent 512-dots (independent load chains -> MLP 4)
static __device__ __forceinline__ void dot512x4(const float4* xv,
                                                const float* p0, const float* p1,
                                                const float* p2, const float* p3,
                                                int lane, float d[4]) {
    const float4* q0 = (const float4*)p0;
    const float4* q1 = (const float4*)p1;
    const float4* q2 = (const float4*)p2;
    const float4* q3 = (const float4*)p3;
    float s0 = 0.f, s1 = 0.f, s2 = 0.f, s3 = 0.f;
#pragma unroll
    for (int i = 0; i < 4; i++) {
        float4 c0 = q0[lane + 32 * i];
        float4 c1 = q1[lane + 32 * i];
        float4 c2 = q2[lane + 32 * i];
        float4 c3 = q3[lane + 32 * i];
        s0 = fmaf(xv[i].x, c0.x, s0); s0 = fmaf(xv[i].y, c0.y, s0);
        s0 = fmaf(xv[i].z, c0.z, s0); s0 = fmaf(xv[i].w, c0.w, s0);
        s1 = fmaf(xv[i].x, c1.x, s1); s1 = fmaf(xv[i].y, c1.y, s1);
        s1 = fmaf(xv[i].z, c1.z, s1); s1 = fmaf(xv[i].w, c1.w, s1);
        s2 = fmaf(xv[i].x, c2.x, s2); s2 = fmaf(xv[i].y, c2.y, s2);
        s2 = fmaf(xv[i].z, c2.z, s2); s2 = fmaf(xv[i].w, c2.w, s2);
        s3 = fmaf(xv[i].x, c3.x, s3); s3 = fmaf(xv[i].y, c3.y, s3);
        s3 = fmaf(xv[i].z, c3.z, s3); s3 = fmaf(xv[i].w, c3.w, s3);
    }
#pragma unroll
    for (int o = 16; o > 0; o >>= 1) {
        s0 += __shfl_xor_sync(0xffffffffu, s0, o);
        s1 += __shfl_xor_sync(0xffffffffu, s1, o);
        s2 += __shfl_xor_sync(0xffffffffu, s2, o);
        s3 += __shfl_xor_sync(0xffffffffu, s3, o);
    }
    d[0] = s0; d[1] = s1; d[2] = s2; d[3] = s3;
}

// ---------------------------------------------------------------------------
// prep (small): centers f32->bf16 + cnorm (blocks 0..63); presence marks (64..67)
// ---------------------------------------------------------------------------
__global__ void prep_kernel(const float* __restrict__ CT, const int* __restrict__ T) {
    if (blockIdx.x >= 64) {
        int base = (blockIdx.x - 64) * 2048 + threadIdx.x;
#pragma unroll
        for (int k = 0; k < 8; k++) g_present[T[base + 256 * k]] = 1;
        return;
    }
    int row  = blockIdx.x * 8 + (threadIdx.x >> 5);
    int lane = threadIdx.x & 31;
    const float* src = CT + (size_t)row * DD;
    float s = 0.f;
    const float4* p4 = (const float4*)src;
#pragma unroll
    for (int i = 0; i < 4; i++) {
        float4 v = p4[lane + 32 * i];
        s = sq4(v, s);
        uint2 hv;
        hv.x = packbf(v.x, v.y);
        hv.y = packbf(v.z, v.w);
        *(uint2*)(g_ch + (size_t)row * DD + (size_t)(lane + 32 * i) * 4) = hv;
    }
#pragma unroll
    for (int o = 16; o > 0; o >>= 1) s += __shfl_xor_sync(0xffffffffu, s, o);
    if (lane == 0) g_cnorm[row] = s;
}

// ---------------------------------------------------------------------------
// main: M32 x N512 bf16 HMMA, 512 threads, 16 warps (2 wr x 8 wc), warp tile
// m16 x n64, SW64 swizzle (64B rows), 2 CTAs per SM for cross-CTA overlap.
// ---------------------------------------------------------------------------
__global__ __launch_bounds__(NTH, 2) void main_kernel(
    const float* __restrict__ X, const float* __restrict__ CT,
    const int* __restrict__ T, float* out, int out_size)
{
    extern __shared__ char smem[];
    const uint32_t sb = s2u(smem);
    const int tid = threadIdx.x, lane = tid & 31, wid = tid >> 5;
    const int wr = wid >> 3, wc = wid & 7;
    const float INF = __int_as_float(0x7f800000);

    float* cn     = (float*)(smem + SM_CN);
    int*   tg     = (int*)(smem + SM_TG);
    float* sxn    = (float*)(smem + SM_XN);
    float* rowmin = (float*)(smem + SM_RM);
    int*   scnt   = (int*)(smem + SM_SCNT);
    unsigned short* scand = (unsigned short*)(smem + SM_CAND);
    float* red    = (float*)(smem + SM_RED);
    float* lp     = (float*)(smem + SM_LP);
    float* fin    = (float*)(smem + SM_FIN);

    cn[tid] = g_present[tid] ? g_cnorm[tid] : INF;
    if (tid < MT) { tg[tid] = T[blockIdx.x * MT + tid]; scnt[tid] = 0; }

    // ---- A producer: 32 rows x 8 threads (tid<256); 1 float4 -> uint2/stage ----
    const int arow = tid >> 3, aq = tid & 7;
    const float4* Ag = (const float4*)(X + (size_t)(blockIdx.x * MT + arow) * DD);
    const uint32_t aoff_sw = (uint32_t)(arow * 64 + aq * 8)
                           ^ ((uint32_t)((arow >> 1) & 3) << 4);
    float sq = 0.f;

    // ---- B producer: 512 rows x 4 chunks = 2048 cp16 / 512 threads = 4 each ----
    const int brow0 = tid >> 2, bq = tid & 3;
#define BFILL(ST)                                                                 \
    do {                                                                          \
        const int st_ = (ST);                                                     \
        const uint32_t dstb_ = sb + SM_TILE + (uint32_t)(st_ & 1) * STG_B + OFF_B;\
        _Pragma("unroll")                                                         \
        for (int i_ = 0; i_ < 4; i_++) {                                          \
            int row_ = brow0 + 128 * i_;                                          \
            uint32_t off_ = (uint32_t)(row_ * 64)                                 \
                          + (uint32_t)((bq ^ ((row_ >> 1) & 3)) * 16);            \
            cp16(dstb_ + off_, g_ch + (size_t)row_ * DD + st_ * 32 + bq * 8);     \
        }                                                                         \
        asm volatile("cp.async.commit_group;");                                   \
    } while (0)

    // ---- prologue ----
    if (tid < 256) {
#pragma unroll
        for (int st = 0; st < 2; st++) {
            float4 u = Ag[st * 8 + aq];
            sq = sq4(u, sq);
            uint2 hv; hv.x = packbf(u.x, u.y); hv.y = packbf(u.z, u.w);
            *(uint2*)(smem + SM_TILE + st * STG_B + OFF_A + aoff_sw) = hv;
        }
    }
    BFILL(0);
    BFILL(1);
    float4 ar = make_float4(0.f, 0.f, 0.f, 0.f);
    if (tid < 256) ar = Ag[2 * 8 + aq];

    float acc[8][4];
#pragma unroll
    for (int j = 0; j < 8; j++)
#pragma unroll
        for (int e = 0; e < 4; e++) acc[j][e] = 0.f;

    const int rA        = wr * 16 + (lane & 15);
    const uint32_t swzA = (uint32_t)(((lane & 15) >> 1) & 3) << 4;
    const uint32_t kA   = (uint32_t)(lane >> 4) << 4;
    const uint32_t kB   = (uint32_t)((lane >> 3) & 1) << 4;
    const int nB        = ((lane >> 4) << 3) + (lane & 7);
    const uint32_t swzB = (uint32_t)((nB >> 1) & 3) << 4;

    for (int kt = 0; kt < NSTG; kt++) {
        if (kt == NSTG - 1) asm volatile("cp.async.wait_group 0;");
        else                asm volatile("cp.async.wait_group 1;");
        __syncthreads();

        const uint32_t tb    = sb + SM_TILE + (uint32_t)(kt & 1) * STG_B;
        const uint32_t aA0   = tb + OFF_A + (uint32_t)rA * 64;
        const uint32_t bbase = tb + OFF_B + (uint32_t)((wc * 64 + nB) * 64);

#pragma unroll
        for (int kk = 0; kk < 2; kk++) {
            const uint32_t ka = ((uint32_t)(kk * 32) + kA) ^ swzA;
            const uint32_t kb = ((uint32_t)(kk * 32) + kB) ^ swzB;
            uint32_t a[4];
            LDSM4(a[0], a[1], a[2], a[3], aA0 + ka);
#pragma unroll
            for (int nb = 0; nb < 4; nb++) {
                uint32_t b[4];
                LDSM4(b[0], b[1], b[2], b[3], bbase + (uint32_t)(nb * 1024) + kb);
                MMA(acc[nb * 2 + 0], a, b[0], b[1]);
                MMA(acc[nb * 2 + 1], a, b[2], b[3]);
            }
        }
        __syncthreads();
        if (kt + 2 < NSTG) {
            if (tid < 256) {
                sq = sq4(ar, sq);
                uint2 hv; hv.x = packbf(ar.x, ar.y); hv.y = packbf(ar.z, ar.w);
                *(uint2*)(smem + SM_TILE + (size_t)(kt & 1) * STG_B + OFF_A + aoff_sw) = hv;
            }
            BFILL(kt + 2);
            if (kt + 3 < NSTG && tid < 256) ar = Ag[(kt + 3) * 8 + aq];
        }
    }
#undef BFILL

    // ---- row norms: reduce over the 8 q-threads of each row ----
    if (tid < 256) {
        sq += __shfl_xor_sync(0xffffffffu, sq, 1);
        sq += __shfl_xor_sync(0xffffffffu, sq, 2);
        sq += __shfl_xor_sync(0xffffffffu, sq, 4);
        if (aq == 0) sxn[arow] = sq;
    }

    // ---- pass 1: approx row-min over non-own classes ----
    float rmin[2] = {INF, INF};
#pragma unroll
    for (int j = 0; j < 8; j++) {
        const int colb = wc * 64 + j * 8 + (lane & 3) * 2;
#pragma unroll
        for (int e = 0; e < 4; e++) {
            const int cl = colb + (e & 1);
            const int lr = wr * 16 + ((e >> 1) << 3) + (lane >> 2);
            const float v = fmaf(-2.f, acc[j][e], cn[cl]);
            if (cl != tg[lr]) rmin[e >> 1] = fminf(rmin[e >> 1], v);
        }
    }
#pragma unroll
    for (int rr = 0; rr < 2; rr++) {
        float m = rmin[rr];
        m = fminf(m, __shfl_xor_sync(0xffffffffu, m, 1));
        m = fminf(m, __shfl_xor_sync(0xffffffffu, m, 2));
        if ((lane & 3) == 0)
            red[(wr * 16 + rr * 8 + (lane >> 2)) * 8 + wc] = m;
    }
    __syncthreads();
    if (tid < MT) {
        float m = INF;
#pragma unroll
        for (int i = 0; i < 8; i++) m = fminf(m, red[tid * 8 + i]);
        rowmin[tid] = m;
    }
    __syncthreads();

    // ---- pass 2: mark candidates ----
#pragma unroll
    for (int j = 0; j < 8; j++) {
        const int colb = wc * 64 + j * 8 + (lane & 3) * 2;
#pragma unroll
        for (int e = 0; e < 4; e++) {
            const int cl = colb + (e & 1);
            const int lr = wr * 16 + ((e >> 1) << 3) + (lane >> 2);
            const float v = fmaf(-2.f, acc[j][e], cn[cl]);
            if (cl != tg[lr] && v < 1.0e30f && v <= rowmin[lr] + TH) {
                int s = atomicAdd(&scnt[lr], 1);
                if (s < SLOTS) scand[lr * SLOTS + s] = (unsigned short)cl;
            }
        }
    }
    __syncthreads();

    // ---- refine: exact fp32 dots, own + 3 candidates batched; 2 rows/warp ----
#pragma unroll 1
    for (int rr = 0; rr < 2; rr++) {
        const int lr = wid * 2 + rr;
        const int grow = blockIdx.x * MT + lr;
        const float4* xr = (const float4*)(X + (size_t)grow * DD);
        float4 xv[4];
#pragma unroll
        for (int i = 0; i < 4; i++) xv[i] = xr[lane + 32 * i];
        const int own = tg[lr];
        int cnt = scnt[lr]; if (cnt > SLOTS) cnt = SLOTS;
        const int c1 = (cnt > 0) ? scand[lr * SLOTS + 0] : own;
        const int c2 = (cnt > 1) ? scand[lr * SLOTS + 1] : own;
        const int c3 = (cnt > 2) ? scand[lr * SLOTS + 2] : own;
        float d[4];
        dot512x4(xv, CT + (size_t)own * DD, CT + (size_t)c1 * DD,
                 CT + (size_t)c2 * DD, CT + (size_t)c3 * DD, lane, d);
        float vmin = INF;
        if (cnt > 0) vmin = fminf(vmin, cn[c1] - 2.f * d[1]);
        if (cnt > 1) vmin = fminf(vmin, cn[c2] - 2.f * d[2]);
        if (cnt > 2) vmin = fminf(vmin, cn[c3] - 2.f * d[3]);
        for (int i = 3; i < cnt; i++) {   // rare overflow path
            int c = scand[lr * SLOTS + i];
            float dd = dot512(xv, CT + (size_t)c * DD, lane);
            vmin = fminf(vmin, cn[c] - 2.f * dd);
        }
        const float xn = sxn[lr];
        float dap = sqrtf(fmaxf(xn + cn[own] - 2.f * d[0], 1e-12f));
        float dan = sqrtf(fmaxf(xn + vmin, 1e-12f));
        if (lane == 0) {
            lp[2 * lr]     = fmaxf(0.f, dap - dan + 1.f);
            lp[2 * lr + 1] = (dan > dap) ? 1.f : 0.f;
        }
    }
    __syncthreads();

    // ---- per-CTA reduction + global last-block finish ----
    __shared__ int slast;
    if (tid < MT) {   // one warp: 32 rows
        float li = lp[2 * tid], pi = lp[2 * tid + 1];
#pragma unroll
        for (int o = 16; o > 0; o >>= 1) {
            li += __shfl_xor_sync(0xffffffffu, li, o);
            pi += __shfl_xor_sync(0xffffffffu, pi, o);
        }
        if (tid == 0) {
            g_rpart[2 * blockIdx.x]     = li;
            g_rpart[2 * blockIdx.x + 1] = pi;
            __threadfence();
            slast = (atomicAdd(&g_rcount, 1) == NBLK - 1);
        }
    }
    __syncthreads();
    if (slast) {
        float a = 0.f, b = 0.f;
        if (tid < NBLK) { a = g_rpart[2 * tid]; b = g_rpart[2 * tid + 1]; }
#pragma unroll
        for (int o = 16; o > 0; o >>= 1) {
            a += __shfl_xor_sync(0xffffffffu, a, o);
            b += __shfl_xor_sync(0xffffffffu, b, o);
        }
        if (tid < NBLK && (lane == 0)) { fin[wid] = a; fin[8 + wid] = b; }
        __syncthreads();
        if (tid == 0) {
            float sa = 0.f, sb = 0.f;
#pragma unroll
            for (int i = 0; i < 8; i++) { sa += fin[i]; sb += fin[8 + i]; }
            out[0] = sa / (float)BSZ;
            if (out_size > 1) out[1] = sb / (float)BSZ;
            g_rcount = 0;            // reset for next graph replay
        }
    }
}

// ---------------------------------------------------------------------------
extern "C" void kernel_launch(void* const* d_in, const int* in_sizes, int n_in,
                              void* d_out, int out_size) {
    const float* X  = nullptr;
    const float* CT = nullptr;
    const int*   T  = nullptr;
    for (int i = 0; i < n_in; i++) {
        if (in_sizes[i] == BSZ * DD)     X  = (const float*)d_in[i];
        else if (in_sizes[i] == CC * DD) CT = (const float*)d_in[i];
        else if (in_sizes[i] == BSZ)     T  = (const int*)d_in[i];
    }
    cudaFuncSetAttribute(main_kernel,
                         cudaFuncAttributeMaxDynamicSharedMemorySize, SMEM_BYTES);

    prep_kernel<<<68, 256>>>(CT, T);
    main_kernel<<<NBLK, NTH, SMEM_BYTES>>>(X, CT, T, (float*)d_out, out_size);
}

// round 12
// speedup vs baseline: 1.2028x; 1.2028x over previous
#include <cuda_runtime.h>
#include <cuda_bf16.h>
#include <cstdint>

#define BSZ 8192
#define DD  512
#define CC  512
#define MT  64                  // rows per CTA
#define NBLK (BSZ / MT)         // 128 CTAs
#define NSTG 4                  // K chunks of 128 fp8 (128B rows)
#define TH  16.0f               // candidate threshold (~2x 5-sigma fp8 dot error)
#define SLOTS 32
#define NTH 512

// ---- device scratch ----
__device__ unsigned char g_c8[CC * DD];   // centers in e4m3
__device__ float g_cnorm[CC];             // exact fp32 norms
__device__ int   g_present[CC];           // zero-init; only 1s written (idempotent)
__device__ float g_rpart[2 * NBLK];
__device__ int   g_rcount;                // reset by last block each call

// ---- main smem layout (bytes) ----
#define SM_CN    0                   // 512 f
#define SM_TG    2048                // 64 i
#define SM_XN    2304                // 64 f
#define SM_RM    2560                // 64 f
#define SM_SCNT  2816                // 64 i
#define SM_CAND  3072                // 64*32 u16 = 4096
#define SM_RED   7168                // 64*8 f = 2048
#define SM_LP    9216                // 64*2 f = 512
#define SM_FIN   9728                // 8 f
#define SM_TILE  10240               // 1024-aligned
#define OFF_A    0                   // 64 rows x 128B (k128 fp8)
#define OFF_B    8192                // 512 rows x 128B
#define STG_B    73728
#define SMEM_BYTES (SM_TILE + 2 * STG_B)   // 157696

static __device__ __forceinline__ uint32_t s2u(const void* p) {
    uint32_t a;
    asm("{ .reg .u64 t; cvta.to.shared.u64 t, %1; cvt.u32.u64 %0, t; }" : "=r"(a) : "l"(p));
    return a;
}
static __device__ __forceinline__ void cp16(uint32_t dst, const void* src) {
    asm volatile("cp.async.cg.shared.global [%0], [%1], 16;" :: "r"(dst), "l"(src));
}
#define LDSM4(r0, r1, r2, r3, addr)                                             \
    asm volatile("ldmatrix.sync.aligned.m8n8.x4.shared.b16 {%0,%1,%2,%3}, [%4];" \
                 : "=r"(r0), "=r"(r1), "=r"(r2), "=r"(r3) : "r"(addr))
// fp8 e4m3 MMA: m16n8k32, A 4 regs, B 2 regs, C/D 4 f32
#define MMA8(d, a, b0, b1)                                                       \
    asm volatile("mma.sync.aligned.m16n8k32.row.col.f32.e4m3.e4m3.f32 "          \
                 "{%0,%1,%2,%3},{%4,%5,%6,%7},{%8,%9},{%0,%1,%2,%3};"            \
                 : "+f"((d)[0]), "+f"((d)[1]), "+f"((d)[2]), "+f"((d)[3])        \
                 : "r"((a)[0]), "r"((a)[1]), "r"((a)[2]), "r"((a)[3]),           \
                   "r"(b0), "r"(b1))

// pack float4 -> 4 e4m3 bytes (memory order x,y,z,w)
static __device__ __forceinline__ uint32_t pack4_e4m3(float4 v) {
    uint16_t h0, h1;
    asm("cvt.rn.satfinite.e4m3x2.f32 %0, %1, %2;" : "=h"(h0) : "f"(v.y), "f"(v.x));
    asm("cvt.rn.satfinite.e4m3x2.f32 %0, %1, %2;" : "=h"(h1) : "f"(v.w), "f"(v.z));
    return (uint32_t)h0 | ((uint32_t)h1 << 16);
}
static __device__ __forceinline__ float sq4(float4 v, float s) {
    s = fmaf(v.x, v.x, s); s = fmaf(v.y, v.y, s);
    s = fmaf(v.z, v.z, s); s = fmaf(v.w, v.w, s);
    return s;
}
static __device__ __forceinline__ float dot512(const float4* xv, const float* crow, int lane) {
    const float4* c4 = (const float4*)crow;
    float s = 0.f;
#pragma unroll
    for (int i = 0; i < 4; i++) {
        float4 c = c4[lane + 32 * i];
        s = fmaf(xv[i].x, c.x, s); s = fmaf(xv[i].y, c.y, s);
        s = fmaf(xv[i].z, c.z, s); s = fmaf(xv[i].w, c.w, s);
    }
#pragma unroll
    for (int o = 16; o > 0; o >>= 1) s += __shfl_xor_sync(0xffffffffu, s, o);
    return s;
}
// 4 concurrent 512-dots (independent load chains -> MLP 4)
static __device__ __forceinline__ void dot512x4(const float4* xv,
                                                const float* p0, const float* p1,
                                                const float* p2, const float* p3,
                                                int lane, float d[4]) {
    const float4* q0 = (const float4*)p0;
    const float4* q1 = (const float4*)p1;
    const float4* q2 = (const float4*)p2;
    const float4* q3 = (const float4*)p3;
    float s0 = 0.f, s1 = 0.f, s2 = 0.f, s3 = 0.f;
#pragma unroll
    for (int i = 0; i < 4; i++) {
        float4 c0 = q0[lane + 32 * i];
        float4 c1 = q1[lane + 32 * i];
        float4 c2 = q2[lane + 32 * i];
        float4 c3 = q3[lane + 32 * i];
        s0 = fmaf(xv[i].x, c0.x, s0); s0 = fmaf(xv[i].y, c0.y, s0);
        s0 = fmaf(xv[i].z, c0.z, s0); s0 = fmaf(xv[i].w, c0.w, s0);
        s1 = fmaf(xv[i].x, c1.x, s1); s1 = fmaf(xv[i].y, c1.y, s1);
        s1 = fmaf(xv[i].z, c1.z, s1); s1 = fmaf(xv[i].w, c1.w, s1);
        s2 = fmaf(xv[i].x, c2.x, s2); s2 = fmaf(xv[i].y, c2.y, s2);
        s2 = fmaf(xv[i].z, c2.z, s2); s2 = fmaf(xv[i].w, c2.w, s2);
        s3 = fmaf(xv[i].x, c3.x, s3); s3 = fmaf(xv[i].y, c3.y, s3);
        s3 = fmaf(xv[i].z, c3.z, s3); s3 = fmaf(xv[i].w, c3.w, s3);
    }
#pragma unroll
    for (int o = 16; o > 0; o >>= 1) {
        s0 += __shfl_xor_sync(0xffffffffu, s0, o);
        s1 += __shfl_xor_sync(0xffffffffu, s1, o);
        s2 += __shfl_xor_sync(0xffffffffu, s2, o);
        s3 += __shfl_xor_sync(0xffffffffu, s3, o);
    }
    d[0] = s0; d[1] = s1; d[2] = s2; d[3] = s3;
}

// ---------------------------------------------------------------------------
// prep (small): centers f32->e4m3 + exact cnorm (blocks 0..63); marks (64..67)
// ---------------------------------------------------------------------------
__global__ void prep_kernel(const float* __restrict__ CT, const int* __restrict__ T) {
    if (blockIdx.x >= 64) {
        int base = (blockIdx.x - 64) * 2048 + threadIdx.x;
#pragma unroll
        for (int k = 0; k < 8; k++) g_present[T[base + 256 * k]] = 1;
        return;
    }
    int row  = blockIdx.x * 8 + (threadIdx.x >> 5);
    int lane = threadIdx.x & 31;
    const float4* p4 = (const float4*)(CT + (size_t)row * DD);
    float s = 0.f;
    uint4 out;
    {
        float4 v0 = p4[lane * 4 + 0], v1 = p4[lane * 4 + 1];
        float4 v2 = p4[lane * 4 + 2], v3 = p4[lane * 4 + 3];
        s = sq4(v0, s); s = sq4(v1, s); s = sq4(v2, s); s = sq4(v3, s);
        out.x = pack4_e4m3(v0); out.y = pack4_e4m3(v1);
        out.z = pack4_e4m3(v2); out.w = pack4_e4m3(v3);
    }
    *(uint4*)(g_c8 + (size_t)row * DD + (size_t)lane * 16) = out;
#pragma unroll
    for (int o = 16; o > 0; o >>= 1) s += __shfl_xor_sync(0xffffffffu, s, o);
    if (lane == 0) g_cnorm[row] = s;
}

// ---------------------------------------------------------------------------
// main: M64 x N512 fp8 (e4m3) HMMA approx GEMM + inline X conversion +
// row norms + candidate marking + exact fp32 refine + global reduction.
// 512 threads, 16 warps (2 wr x 8 wc), warp tile m32 x n64, k32 per MMA.
// ---------------------------------------------------------------------------
__global__ __launch_bounds__(NTH, 1) void main_kernel(
    const float* __restrict__ X, const float* __restrict__ CT,
    const int* __restrict__ T, float* out, int out_size)
{
    extern __shared__ char smem[];
    const uint32_t sb = s2u(smem);
    const int tid = threadIdx.x, lane = tid & 31, wid = tid >> 5;
    const int wr = wid >> 3, wc = wid & 7;
    const float INF = __int_as_float(0x7f800000);

    float* cn     = (float*)(smem + SM_CN);
    int*   tg     = (int*)(smem + SM_TG);
    float* sxn    = (float*)(smem + SM_XN);
    float* rowmin = (float*)(smem + SM_RM);
    int*   scnt   = (int*)(smem + SM_SCNT);
    unsigned short* scand = (unsigned short*)(smem + SM_CAND);
    float* red    = (float*)(smem + SM_RED);
    float* lp     = (float*)(smem + SM_LP);
    float* fin    = (float*)(smem + SM_FIN);

    if (tid < CC) cn[tid] = g_present[tid] ? g_cnorm[tid] : INF;
    if (tid < MT) { tg[tid] = T[blockIdx.x * MT + tid]; scnt[tid] = 0; }

    // ---- A producer: 64 rows x 8 threads; each converts 16 f32 -> 16 fp8 ----
    const int arow = tid >> 3, aq = tid & 7;
    const float4* Ag = (const float4*)(X + (size_t)(blockIdx.x * MT + arow) * DD);
    const uint32_t aoff0 = (uint32_t)(arow * 128 + aq * 16);
    const uint32_t aoff_sw = aoff0 ^ ((aoff0 >> 3) & 0x70);
    float sq = 0.f;

    // ---- B producer: 512 rows x 8 chunks = 4096 cp16 / 512 threads = 8 each ----
    const int brow0 = tid >> 3, bq = tid & 7;
#define BFILL(ST)                                                                 \
    do {                                                                          \
        const int st_ = (ST);                                                     \
        const uint32_t dstb_ = sb + SM_TILE + (uint32_t)(st_ & 1) * STG_B + OFF_B;\
        _Pragma("unroll")                                                         \
        for (int i_ = 0; i_ < 8; i_++) {                                          \
            int row_ = brow0 + 64 * i_;                                           \
            uint32_t off_ = (uint32_t)(row_ * 128 + bq * 16);                     \
            off_ ^= ((off_ >> 3) & 0x70);                                         \
            cp16(dstb_ + off_, g_c8 + (size_t)row_ * DD + st_ * 128 + bq * 16);   \
        }                                                                         \
        asm volatile("cp.async.commit_group;");                                   \
    } while (0)

#define AFILL(ST)                                                                 \
    do {                                                                          \
        const int st_ = (ST);                                                     \
        float4 u0 = Ag[st_ * 32 + aq * 4 + 0];                                    \
        float4 u1 = Ag[st_ * 32 + aq * 4 + 1];                                    \
        float4 u2 = Ag[st_ * 32 + aq * 4 + 2];                                    \
        float4 u3 = Ag[st_ * 32 + aq * 4 + 3];                                    \
        sq = sq4(u0, sq); sq = sq4(u1, sq); sq = sq4(u2, sq); sq = sq4(u3, sq);   \
        uint4 pv;                                                                 \
        pv.x = pack4_e4m3(u0); pv.y = pack4_e4m3(u1);                             \
        pv.z = pack4_e4m3(u2); pv.w = pack4_e4m3(u3);                             \
        *(uint4*)(smem + SM_TILE + (size_t)(st_ & 1) * STG_B + OFF_A + aoff_sw) = pv; \
    } while (0)

    // ---- prologue ----
    AFILL(0);
    AFILL(1);
    BFILL(0);
    BFILL(1);

    float acc[2][8][4];
#pragma unroll
    for (int mb = 0; mb < 2; mb++)
#pragma unroll
        for (int j = 0; j < 8; j++)
#pragma unroll
            for (int e = 0; e < 4; e++) acc[mb][j][e] = 0.f;

    const int rA       = wr * 32 + (lane & 15);
    const uint32_t swz = (uint32_t)(lane & 7) << 4;
    const uint32_t kA  = (uint32_t)(lane >> 4) << 4;
    const uint32_t kB  = (uint32_t)((lane >> 3) & 1) << 4;
    const int nB       = ((lane >> 4) << 3) + (lane & 7);

    for (int kt = 0; kt < NSTG; kt++) {
        if (kt == NSTG - 1) asm volatile("cp.async.wait_group 0;");
        else                asm volatile("cp.async.wait_group 1;");
        __syncthreads();

        const uint32_t tb    = sb + SM_TILE + (uint32_t)(kt & 1) * STG_B;
        const uint32_t aA0   = tb + OFF_A + (uint32_t)rA * 128;
        const uint32_t bbase = tb + OFF_B + (uint32_t)((wc * 64 + nB) * 128);

#pragma unroll
        for (int kk = 0; kk < 4; kk++) {    // 4 x k32 per 128B row
            const uint32_t ka = ((uint32_t)(kk * 32) + kA) ^ swz;
            const uint32_t kb = ((uint32_t)(kk * 32) + kB) ^ swz;
            uint32_t ah[2][4];
            LDSM4(ah[0][0], ah[0][1], ah[0][2], ah[0][3], aA0 + ka);
            LDSM4(ah[1][0], ah[1][1], ah[1][2], ah[1][3], aA0 + 16 * 128 + ka);
#pragma unroll
            for (int nb = 0; nb < 4; nb++) {
                uint32_t b[4];
                LDSM4(b[0], b[1], b[2], b[3], bbase + (uint32_t)(nb * 2048) + kb);
                MMA8(acc[0][nb * 2 + 0], ah[0], b[0], b[1]);
                MMA8(acc[0][nb * 2 + 1], ah[0], b[2], b[3]);
                MMA8(acc[1][nb * 2 + 0], ah[1], b[0], b[1]);
                MMA8(acc[1][nb * 2 + 1], ah[1], b[2], b[3]);
            }
        }
        __syncthreads();
        if (kt + 2 < NSTG) {
            AFILL(kt + 2);
            BFILL(kt + 2);
        }
    }
#undef BFILL
#undef AFILL

    // ---- row norms: reduce over the 8 q-threads of each row ----
    sq += __shfl_xor_sync(0xffffffffu, sq, 1);
    sq += __shfl_xor_sync(0xffffffffu, sq, 2);
    sq += __shfl_xor_sync(0xffffffffu, sq, 4);
    if (aq == 0) sxn[arow] = sq;

    // ---- pass 1: approx row-min over non-own classes ----
    float rmin[2][2];
#pragma unroll
    for (int mb = 0; mb < 2; mb++) { rmin[mb][0] = INF; rmin[mb][1] = INF; }
#pragma unroll
    for (int mb = 0; mb < 2; mb++)
#pragma unroll
        for (int j = 0; j < 8; j++) {
            const int colb = wc * 64 + j * 8 + (lane & 3) * 2;
#pragma unroll
            for (int e = 0; e < 4; e++) {
                const int cl = colb + (e & 1);
                const int lr = wr * 32 + mb * 16 + ((e >> 1) << 3) + (lane >> 2);
                const float v = fmaf(-2.f, acc[mb][j][e], cn[cl]);
                if (cl != tg[lr]) rmin[mb][e >> 1] = fminf(rmin[mb][e >> 1], v);
            }
        }
#pragma unroll
    for (int mb = 0; mb < 2; mb++)
#pragma unroll
        for (int rr = 0; rr < 2; rr++) {
            float m = rmin[mb][rr];
            m = fminf(m, __shfl_xor_sync(0xffffffffu, m, 1));
            m = fminf(m, __shfl_xor_sync(0xffffffffu, m, 2));
            if ((lane & 3) == 0)
                red[(wr * 32 + mb * 16 + rr * 8 + (lane >> 2)) * 8 + wc] = m;
        }
    __syncthreads();
    if (tid < MT) {
        float m = INF;
#pragma unroll
        for (int i = 0; i < 8; i++) m = fminf(m, red[tid * 8 + i]);
        rowmin[tid] = m;
    }
    __syncthreads();

    // ---- pass 2: mark candidates ----
#pragma unroll
    for (int mb = 0; mb < 2; mb++)
#pragma unroll
        for (int j = 0; j < 8; j++) {
            const int colb = wc * 64 + j * 8 + (lane & 3) * 2;
#pragma unroll
            for (int e = 0; e < 4; e++) {
                const int cl = colb + (e & 1);
                const int lr = wr * 32 + mb * 16 + ((e >> 1) << 3) + (lane >> 2);
                const float v = fmaf(-2.f, acc[mb][j][e], cn[cl]);
                if (cl != tg[lr] && v < 1.0e30f && v <= rowmin[lr] + TH) {
                    int s = atomicAdd(&scnt[lr], 1);
                    if (s < SLOTS) scand[lr * SLOTS + s] = (unsigned short)cl;
                }
            }
        }
    __syncthreads();

    // ---- refine: exact fp32 dots, own + 3 candidates batched; 4 rows/warp ----
#pragma unroll 1
    for (int rr = 0; rr < 4; rr++) {
        const int lr = wid * 4 + rr;
        const int grow = blockIdx.x * MT + lr;
        const float4* xr = (const float4*)(X + (size_t)grow * DD);
        float4 xv[4];
#pragma unroll
        for (int i = 0; i < 4; i++) xv[i] = xr[lane + 32 * i];
        const int own = tg[lr];
        int cnt = scnt[lr]; if (cnt > SLOTS) cnt = SLOTS;
        const int c1 = (cnt > 0) ? scand[lr * SLOTS + 0] : own;
        const int c2 = (cnt > 1) ? scand[lr * SLOTS + 1] : own;
        const int c3 = (cnt > 2) ? scand[lr * SLOTS + 2] : own;
        float d[4];
        dot512x4(xv, CT + (size_t)own * DD, CT + (size_t)c1 * DD,
                 CT + (size_t)c2 * DD, CT + (size_t)c3 * DD, lane, d);
        float vmin = INF;
        if (cnt > 0) vmin = fminf(vmin, cn[c1] - 2.f * d[1]);
        if (cnt > 1) vmin = fminf(vmin, cn[c2] - 2.f * d[2]);
        if (cnt > 2) vmin = fminf(vmin, cn[c3] - 2.f * d[3]);
        for (int i = 3; i < cnt; i++) {   // overflow path
            int c = scand[lr * SLOTS + i];
            float dd = dot512(xv, CT + (size_t)c * DD, lane);
            vmin = fminf(vmin, cn[c] - 2.f * dd);
        }
        const float xn = sxn[lr];
        float dap = sqrtf(fmaxf(xn + cn[own] - 2.f * d[0], 1e-12f));
        float dan = sqrtf(fmaxf(xn + vmin, 1e-12f));
        if (lane == 0) {
            lp[2 * lr]     = fmaxf(0.f, dap - dan + 1.f);
            lp[2 * lr + 1] = (dan > dap) ? 1.f : 0.f;
        }
    }
    __syncthreads();

    // ---- per-CTA reduction + global last-block finish ----
    __shared__ int slast;
    if (tid < MT) {
        float li = lp[2 * tid], pi = lp[2 * tid + 1];
#pragma unroll
        for (int o = 16; o > 0; o >>= 1) {
            li += __shfl_xor_sync(0xffffffffu, li, o);
            pi += __shfl_xor_sync(0xffffffffu, pi, o);
        }
        if ((tid & 31) == 0) { fin[tid >> 5] = li; fin[4 + (tid >> 5)] = pi; }
    }
    __syncthreads();
    if (tid == 0) {
        g_rpart[2 * blockIdx.x]     = fin[0] + fin[1];
        g_rpart[2 * blockIdx.x + 1] = fin[4] + fin[5];
        __threadfence();
        slast = (atomicAdd(&g_rcount, 1) == NBLK - 1);
    }
    __syncthreads();
    if (slast) {
        float a = 0.f, b = 0.f;
        if (tid < NBLK) { a = g_rpart[2 * tid]; b = g_rpart[2 * tid + 1]; }
#pragma unroll
        for (int o = 16; o > 0; o >>= 1) {
            a += __shfl_xor_sync(0xffffffffu, a, o);
            b += __shfl_xor_sync(0xffffffffu, b, o);
        }
        if (tid < NBLK && (tid & 31) == 0) { fin[tid >> 5] = a; fin[4 + (tid >> 5)] = b; }
        __syncthreads();
        if (tid == 0) {
            float sa = fin[0] + fin[1] + fin[2] + fin[3];
            float sb = fin[4] + fin[5] + fin[6] + fin[7];
            out[0] = sa / (float)BSZ;
            if (out_size > 1) out[1] = sb / (float)BSZ;
            g_rcount = 0;            // reset for next graph replay
        }
    }
}

// ---------------------------------------------------------------------------
extern "C" void kernel_launch(void* const* d_in, const int* in_sizes, int n_in,
                              void* d_out, int out_size) {
    const float* X  = nullptr;
    const float* CT = nullptr;
    const int*   T  = nullptr;
    for (int i = 0; i < n_in; i++) {
        if (in_sizes[i] == BSZ * DD)     X  = (const float*)d_in[i];
        else if (in_sizes[i] == CC * DD) CT = (const float*)d_in[i];
        else if (in_sizes[i] == BSZ)     T  = (const int*)d_in[i];
    }
    cudaFuncSetAttribute(main_kernel,
                         cudaFuncAttributeMaxDynamicSharedMemorySize, SMEM_BYTES);

    prep_kernel<<<68, 256>>>(CT, T);
    main_kernel<<<NBLK, NTH, SMEM_BYTES>>>(X, CT, T, (float*)d_out, out_size);
}

// round 13
// speedup vs baseline: 1.3980x; 1.1623x over previous
#include <cuda_runtime.h>
#include <cuda_bf16.h>
#include <cstdint>

#define BSZ 8192
#define DD  512
#define CC  512
#define MT  64                  // rows per CTA
#define NBLK (BSZ / MT)         // 128 CTAs
#define NSTG 8                  // K chunks of 64
#define TH  3.0f
#define SLOTS 16
#define NTH 512

// ---- device scratch ----
__device__ __nv_bfloat16 g_ch[CC * DD];
__device__ float g_cnorm[CC];
__device__ int   g_present[CC];      // zero-init; only 1s written (idempotent)
__device__ float g_rpart[2 * NBLK];
__device__ int   g_rcount;           // reset by last block each call

// ---- main smem layout (bytes) ----
#define SM_CN    0                   // 512 f
#define SM_TG    2048                // 64 i
#define SM_XN    2304                // 64 f
#define SM_RM    2560                // 64 f
#define SM_SCNT  2816                // 64 i
#define SM_CAND  3072                // 64*16 u16
#define SM_RED   5120                // 64*8 f
#define SM_LP    7168                // 64*2 f
#define SM_FIN   7680                // 8 f
#define SM_TILE  8192                // 1024-aligned
#define OFF_A    0                   // 64 rows x 128B
#define OFF_B    8192                // 512 rows x 128B
#define STG_S    73728               // one stage (A+B)
#define SMEM_BYTES (SM_TILE + 3 * STG_S)   // 229376 (triple buffer)

static __device__ __forceinline__ uint32_t s2u(const void* p) {
    uint32_t a;
    asm("{ .reg .u64 t; cvta.to.shared.u64 t, %1; cvt.u32.u64 %0, t; }" : "=r"(a) : "l"(p));
    return a;
}
static __device__ __forceinline__ void cp16(uint32_t dst, const void* src) {
    asm volatile("cp.async.cg.shared.global [%0], [%1], 16;" :: "r"(dst), "l"(src));
}
#define LDSM4(r0, r1, r2, r3, addr)                                             \
    asm volatile("ldmatrix.sync.aligned.m8n8.x4.shared.b16 {%0,%1,%2,%3}, [%4];" \
                 : "=r"(r0), "=r"(r1), "=r"(r2), "=r"(r3) : "r"(addr))
#define MMA(d, a, b0, b1)                                                        \
    asm volatile("mma.sync.aligned.m16n8k16.row.col.f32.bf16.bf16.f32 "          \
                 "{%0,%1,%2,%3},{%4,%5,%6,%7},{%8,%9},{%0,%1,%2,%3};"            \
                 : "+f"((d)[0]), "+f"((d)[1]), "+f"((d)[2]), "+f"((d)[3])        \
                 : "r"((a)[0]), "r"((a)[1]), "r"((a)[2]), "r"((a)[3]),           \
                   "r"(b0), "r"(b1))

static __device__ __forceinline__ uint32_t packbf(float x, float y) {
    return ((uint32_t)__bfloat16_as_ushort(__float2bfloat16(y)) << 16)
         | __bfloat16_as_ushort(__float2bfloat16(x));
}
static __device__ __forceinline__ uint4 cvt8(float4 a, float4 b) {
    uint4 r;
    r.x = packbf(a.x, a.y); r.y = packbf(a.z, a.w);
    r.z = packbf(b.x, b.y); r.w = packbf(b.z, b.w);
    return r;
}
static __device__ __forceinline__ float sq4(float4 v, float s) {
    s = fmaf(v.x, v.x, s); s = fmaf(v.y, v.y, s);
    s = fmaf(v.z, v.z, s); s = fmaf(v.w, v.w, s);
    return s;
}
static __device__ __forceinline__ float dot512(const float4* xv, const float* crow, int lane) {
    const float4* c4 = (const float4*)crow;
    float s = 0.f;
#pragma unroll
    for (int i = 0; i < 4; i++) {
        float4 c = c4[lane + 32 * i];
        s = fmaf(xv[i].x, c.x, s); s = fmaf(xv[i].y, c.y, s);
        s = fmaf(xv[i].z, c.z, s); s = fmaf(xv[i].w, c.w, s);
    }
#pragma unroll
    for (int o = 16; o > 0; o >>= 1) s += __shfl_xor_sync(0xffffffffu, s, o);
    return s;
}

// ---------------------------------------------------------------------------
// prep (small): centers f32->bf16 + cnorm (blocks 0..63); presence marks (64..67)
// ---------------------------------------------------------------------------
__global__ void prep_kernel(const float* __restrict__ CT, const int* __restrict__ T) {
    if (blockIdx.x >= 64) {
        int base = (blockIdx.x - 64) * 2048 + threadIdx.x;
#pragma unroll
        for (int k = 0; k < 8; k++) g_present[T[base + 256 * k]] = 1;
        return;
    }
    int row  = blockIdx.x * 8 + (threadIdx.x >> 5);
    int lane = threadIdx.x & 31;
    const float* src = CT + (size_t)row * DD;
    float s = 0.f;
    const float4* p4 = (const float4*)src;
#pragma unroll
    for (int i = 0; i < 4; i++) {
        float4 v = p4[lane + 32 * i];
        s = sq4(v, s);
        uint2 hv;
        hv.x = packbf(v.x, v.y);
        hv.y = packbf(v.z, v.w);
        *(uint2*)(g_ch + (size_t)row * DD + (size_t)(lane + 32 * i) * 4) = hv;
    }
#pragma unroll
    for (int o = 16; o > 0; o >>= 1) s += __shfl_xor_sync(0xffffffffu, s, o);
    if (lane == 0) g_cnorm[row] = s;
}

// ---------------------------------------------------------------------------
// main: M64 x N512 bf16 HMMA, 512 threads, 16 warps (2 wr x 8 wc), warp tile
// m32 x n64. TRIPLE-buffered stages -> ONE __syncthreads per stage (the WAR
// barrier is removed: fills at iter kt target buffer (kt+2)%3 = (kt-1)%3,
// whose readers all passed the top-of-kt barrier).
// ---------------------------------------------------------------------------
__global__ __launch_bounds__(NTH, 1) void main_kernel(
    const float* __restrict__ X, const float* __restrict__ CT,
    const int* __restrict__ T, float* out, int out_size)
{
    extern __shared__ char smem[];
    const uint32_t sb = s2u(smem);
    const int tid = threadIdx.x, lane = tid & 31, wid = tid >> 5;
    const int wr = wid >> 3, wc = wid & 7;
    const float INF = __int_as_float(0x7f800000);

    float* cn     = (float*)(smem + SM_CN);
    int*   tg     = (int*)(smem + SM_TG);
    float* sxn    = (float*)(smem + SM_XN);
    float* rowmin = (float*)(smem + SM_RM);
    int*   scnt   = (int*)(smem + SM_SCNT);
    unsigned short* scand = (unsigned short*)(smem + SM_CAND);
    float* red    = (float*)(smem + SM_RED);
    float* lp     = (float*)(smem + SM_LP);
    float* fin    = (float*)(smem + SM_FIN);

    if (tid < CC) cn[tid] = g_present[tid] ? g_cnorm[tid] : INF;
    if (tid < MT) { tg[tid] = T[blockIdx.x * MT + tid]; scnt[tid] = 0; }

    // ---- A producer: 64 rows x 8 threads; each converts 2 float4 -> uint4 ----
    const int arow = tid >> 3, aq = tid & 7;
    const float4* Ag = (const float4*)(X + (size_t)(blockIdx.x * MT + arow) * DD);
    const uint32_t aoff0 = (uint32_t)(arow * 128 + aq * 16);
    const uint32_t aoff_sw = aoff0 ^ ((aoff0 >> 3) & 0x70);
    float sq = 0.f;

    // ---- B producer: 512 rows x 8 chunks = 4096 cp16 / 512 threads = 8 each ----
    const int brow0 = tid >> 3, bq = tid & 7;
#define BFILL(ST, BUF)                                                            \
    do {                                                                          \
        const int st_ = (ST);                                                     \
        const uint32_t dstb_ = sb + SM_TILE + (uint32_t)(BUF) * STG_S + OFF_B;    \
        _Pragma("unroll")                                                         \
        for (int i_ = 0; i_ < 8; i_++) {                                          \
            int row_ = brow0 + 64 * i_;                                           \
            uint32_t off_ = (uint32_t)(row_ * 128 + bq * 16);                     \
            off_ ^= ((off_ >> 3) & 0x70);                                         \
            cp16(dstb_ + off_, g_ch + (size_t)row_ * DD + st_ * 64 + bq * 8);     \
        }                                                                         \
        asm volatile("cp.async.commit_group;");                                   \
    } while (0)

    // ---- prologue: stages 0,1 into buffers 0,1 ----
#pragma unroll
    for (int st = 0; st < 2; st++) {
        float4 u0 = Ag[st * 16 + aq * 2], u1 = Ag[st * 16 + aq * 2 + 1];
        sq = sq4(u0, sq); sq = sq4(u1, sq);
        *(uint4*)(smem + SM_TILE + st * STG_S + OFF_A + aoff_sw) = cvt8(u0, u1);
    }
    BFILL(0, 0);
    BFILL(1, 1);
    float4 ar0 = Ag[2 * 16 + aq * 2], ar1 = Ag[2 * 16 + aq * 2 + 1];

    float acc[2][8][4];
#pragma unroll
    for (int mb = 0; mb < 2; mb++)
#pragma unroll
        for (int j = 0; j < 8; j++)
#pragma unroll
            for (int e = 0; e < 4; e++) acc[mb][j][e] = 0.f;

    const int rA       = wr * 32 + (lane & 15);
    const uint32_t swz = (uint32_t)(lane & 7) << 4;
    const uint32_t kA  = (uint32_t)(lane >> 4) << 4;
    const uint32_t kB  = (uint32_t)((lane >> 3) & 1) << 4;
    const int nB       = ((lane >> 4) << 3) + (lane & 7);

    int bcur = 0;                       // kt % 3
    for (int kt = 0; kt < NSTG; kt++) {
        if (kt == NSTG - 1) asm volatile("cp.async.wait_group 0;");
        else                asm volatile("cp.async.wait_group 1;");
        __syncthreads();                // the ONLY barrier per stage

        const uint32_t tb    = sb + SM_TILE + (uint32_t)bcur * STG_S;
        const uint32_t aA0   = tb + OFF_A + (uint32_t)rA * 128;
        const uint32_t bbase = tb + OFF_B + (uint32_t)((wc * 64 + nB) * 128);

#pragma unroll
        for (int kk = 0; kk < 4; kk++) {
            const uint32_t ka = ((uint32_t)(kk * 32) + kA) ^ swz;
            const uint32_t kb = ((uint32_t)(kk * 32) + kB) ^ swz;
            uint32_t ah[2][4];
            LDSM4(ah[0][0], ah[0][1], ah[0][2], ah[0][3], aA0 + ka);
            LDSM4(ah[1][0], ah[1][1], ah[1][2], ah[1][3], aA0 + 16 * 128 + ka);
#pragma unroll
            for (int nb = 0; nb < 4; nb++) {
                uint32_t b[4];
                LDSM4(b[0], b[1], b[2], b[3], bbase + (uint32_t)(nb * 2048) + kb);
                MMA(acc[0][nb * 2 + 0], ah[0], b[0], b[1]);
                MMA(acc[0][nb * 2 + 1], ah[0], b[2], b[3]);
                MMA(acc[1][nb * 2 + 0], ah[1], b[0], b[1]);
                MMA(acc[1][nb * 2 + 1], ah[1], b[2], b[3]);
            }
        }
        // fill stage kt+2 into buffer (kt+2)%3 — no barrier needed (see header)
        if (kt + 2 < NSTG) {
            const int bfill = (bcur + 2 >= 3) ? bcur - 1 : bcur + 2;
            sq = sq4(ar0, sq); sq = sq4(ar1, sq);
            *(uint4*)(smem + SM_TILE + (size_t)bfill * STG_S + OFF_A + aoff_sw)
                = cvt8(ar0, ar1);
            BFILL(kt + 2, bfill);
            if (kt + 3 < NSTG) {
                ar0 = Ag[(kt + 3) * 16 + aq * 2];
                ar1 = Ag[(kt + 3) * 16 + aq * 2 + 1];
            }
        }
        bcur = (bcur + 1 >= 3) ? 0 : bcur + 1;
    }
#undef BFILL

    // ---- row norms: reduce over the 8 q-threads of each row ----
    sq += __shfl_xor_sync(0xffffffffu, sq, 1);
    sq += __shfl_xor_sync(0xffffffffu, sq, 2);
    sq += __shfl_xor_sync(0xffffffffu, sq, 4);
    if (aq == 0) sxn[arow] = sq;

    // ---- pass 1: approx row-min over non-own classes ----
    float rmin[2][2];
#pragma unroll
    for (int mb = 0; mb < 2; mb++) { rmin[mb][0] = INF; rmin[mb][1] = INF; }
#pragma unroll
    for (int mb = 0; mb < 2; mb++)
#pragma unroll
        for (int j = 0; j < 8; j++) {
            const int colb = wc * 64 + j * 8 + (lane & 3) * 2;
#pragma unroll
            for (int e = 0; e < 4; e++) {
                const int cl = colb + (e & 1);
                const int lr = wr * 32 + mb * 16 + ((e >> 1) << 3) + (lane >> 2);
                const float v = fmaf(-2.f, acc[mb][j][e], cn[cl]);
                if (cl != tg[lr]) rmin[mb][e >> 1] = fminf(rmin[mb][e >> 1], v);
            }
        }
#pragma unroll
    for (int mb = 0; mb < 2; mb++)
#pragma unroll
        for (int rr = 0; rr < 2; rr++) {
            float m = rmin[mb][rr];
            m = fminf(m, __shfl_xor_sync(0xffffffffu, m, 1));
            m = fminf(m, __shfl_xor_sync(0xffffffffu, m, 2));
            if ((lane & 3) == 0)
                red[(wr * 32 + mb * 16 + rr * 8 + (lane >> 2)) * 8 + wc] = m;
        }
    __syncthreads();
    if (tid < MT) {
        float m = INF;
#pragma unroll
        for (int i = 0; i < 8; i++) m = fminf(m, red[tid * 8 + i]);
        rowmin[tid] = m;
    }
    __syncthreads();

    // ---- pass 2: mark candidates ----
#pragma unroll
    for (int mb = 0; mb < 2; mb++)
#pragma unroll
        for (int j = 0; j < 8; j++) {
            const int colb = wc * 64 + j * 8 + (lane & 3) * 2;
#pragma unroll
            for (int e = 0; e < 4; e++) {
                const int cl = colb + (e & 1);
                const int lr = wr * 32 + mb * 16 + ((e >> 1) << 3) + (lane >> 2);
                const float v = fmaf(-2.f, acc[mb][j][e], cn[cl]);
                if (cl != tg[lr] && v < 1.0e30f && v <= rowmin[lr] + TH) {
                    int s = atomicAdd(&scnt[lr], 1);
                    if (s < SLOTS) scand[lr * SLOTS + s] = (unsigned short)cl;
                }
            }
        }
    __syncthreads();

    // ---- refine: exact fp32 dots; warp w handles rows w*4..w*4+3 ----
#pragma unroll 1
    for (int rr = 0; rr < 4; rr++) {
        const int lr = wid * 4 + rr;
        const int grow = blockIdx.x * MT + lr;
        const float4* xr = (const float4*)(X + (size_t)grow * DD);
        float4 xv[4];
#pragma unroll
        for (int i = 0; i < 4; i++) xv[i] = xr[lane + 32 * i];
        const int own = tg[lr];
        const float dot_own = dot512(xv, CT + (size_t)own * DD, lane);
        int cnt = scnt[lr]; if (cnt > SLOTS) cnt = SLOTS;
        float vmin = INF;
        for (int i = 0; i < cnt; i++) {
            int c = scand[lr * SLOTS + i];
            float d = dot512(xv, CT + (size_t)c * DD, lane);
            vmin = fminf(vmin, cn[c] - 2.f * d);
        }
        const float xn = sxn[lr];
        float dap = sqrtf(fmaxf(xn + cn[own] - 2.f * dot_own, 1e-12f));
        float dan = sqrtf(fmaxf(xn + vmin, 1e-12f));
        if (lane == 0) {
            lp[2 * lr]     = fmaxf(0.f, dap - dan + 1.f);
            lp[2 * lr + 1] = (dan > dap) ? 1.f : 0.f;
        }
    }
    __syncthreads();

    // ---- per-CTA reduction + global last-block finish ----
    __shared__ int slast;
    if (tid < MT) {
        float li = lp[2 * tid], pi = lp[2 * tid + 1];
#pragma unroll
        for (int o = 16; o > 0; o >>= 1) {
            li += __shfl_xor_sync(0xffffffffu, li, o);
            pi += __shfl_xor_sync(0xffffffffu, pi, o);
        }
        if ((tid & 31) == 0) { fin[tid >> 5] = li; fin[4 + (tid >> 5)] = pi; }
    }
    __syncthreads();
    if (tid == 0) {
        g_rpart[2 * blockIdx.x]     = fin[0] + fin[1];
        g_rpart[2 * blockIdx.x + 1] = fin[4] + fin[5];
        __threadfence();
        slast = (atomicAdd(&g_rcount, 1) == NBLK - 1);
    }
    __syncthreads();
    if (slast) {
        float a = 0.f, b = 0.f;
        if (tid < NBLK) { a = g_rpart[2 * tid]; b = g_rpart[2 * tid + 1]; }
#pragma unroll
        for (int o = 16; o > 0; o >>= 1) {
            a += __shfl_xor_sync(0xffffffffu, a, o);
            b += __shfl_xor_sync(0xffffffffu, b, o);
        }
        if (tid < NBLK && (tid & 31) == 0) { fin[tid >> 5] = a; fin[4 + (tid >> 5)] = b; }
        __syncthreads();
        if (tid == 0) {
            float sa = fin[0] + fin[1] + fin[2] + fin[3];
            float sb = fin[4] + fin[5] + fin[6] + fin[7];
            out[0] = sa / (float)BSZ;
            if (out_size > 1) out[1] = sb / (float)BSZ;
            g_rcount = 0;            // reset for next graph replay
        }
    }
}

// ---------------------------------------------------------------------------
extern "C" void kernel_launch(void* const* d_in, const int* in_sizes, int n_in,
                              void* d_out, int out_size) {
    const float* X  = nullptr;
    const float* CT = nullptr;
    const int*   T  = nullptr;
    for (int i = 0; i < n_in; i++) {
        if (in_sizes[i] == BSZ * DD)     X  = (const float*)d_in[i];
        else if (in_sizes[i] == CC * DD) CT = (const float*)d_in[i];
        else if (in_sizes[i] == BSZ)     T  = (const int*)d_in[i];
    }
    cudaFuncSetAttribute(main_kernel,
                         cudaFuncAttributeMaxDynamicSharedMemorySize, SMEM_BYTES);

    prep_kernel<<<68, 256>>>(CT, T);
    main_kernel<<<NBLK, NTH, SMEM_BYTES>>>(X, CT, T, (float*)d_out, out_size);
}